// round 7
// baseline (speedup 1.0000x reference)
#include <cuda_runtime.h>
#include <math.h>

// Problem constants
#define Bb 8
#define Cc 256
#define Hh 128
#define Ww 128
#define Kk 20
#define HW (Hh * Ww)          // 16384
#define HID 128               // C/2
#define NOUT 4

// Scratch (device globals — no allocation allowed)
__device__ unsigned char g_conn[Bb * HW];            // argmax class per pixel
__device__ float         g_vec [Bb * Kk * Cc];       // max(segment_max, 0)

// ---------------------------------------------------------------------------
// Kernel 1: per-pixel argmax over K classes, fused with the encoded_classes
// pass-through copy into d_out, plus zeroing of g_vec.
// 65536 threads, each handles 2 consecutive pixels via float2 (256B/warp,
// fully coalesced) -> 2048 warps chip-wide, enough MLP to saturate HBM.
// ---------------------------------------------------------------------------
__global__ void k_argmax(const float* __restrict__ cls,
                         float* __restrict__ out_cls)
{
    int tid = blockIdx.x * blockDim.x + threadIdx.x;   // 0 .. 65535

    // zero the vec accumulator (40960 floats)
    if (tid < Bb * Kk * Cc)
        g_vec[tid] = 0.0f;

    int b  = tid >> 13;        // / (HW/2)
    int p2 = tid & 8191;       // % (HW/2)

    const float2* c2 = (const float2*)cls;
    float2*       o2 = (float2*)out_cls;

    float m0, m1;
    int   i0 = 0, i1 = 0;

#pragma unroll
    for (int k = 0; k < Kk; k++) {
        int idx = ((b * Kk + k) << 13) + p2;
        float2 v = c2[idx];
        o2[idx] = v;                       // pass-through copy
        if (k == 0) {
            m0 = v.x; m1 = v.y;
        } else {
            if (v.x > m0) { m0 = v.x; i0 = k; }
            if (v.y > m1) { m1 = v.y; i1 = k; }
        }
    }
    ((uchar2*)g_conn)[tid] = make_uchar2((unsigned char)i0, (unsigned char)i1);
}

// ---------------------------------------------------------------------------
// Kernel 2: segment max. grid = (8 pixel-chunks, C/8, B), block = 256 (8 warps).
// Warp w owns channel blockIdx.y*8+w. Shared acc laid out [warp][k][lane] so
// each lane only touches its own bank column -> conflict-free, atomic-free RMW.
// Accumulator starts at 0, which implements max(segmax, 0) exactly, and makes
// all values >= 0 so int atomicMax == float max.
// ---------------------------------------------------------------------------
__global__ void k_segmax(const float* __restrict__ enc)
{
    __shared__ float acc[8 * Kk * 32];     // 20 KB

    int tid  = threadIdx.x;
    int w    = tid >> 5;
    int lane = tid & 31;

    for (int i = tid; i < 8 * Kk * 32; i += 256)
        acc[i] = 0.0f;
    __syncthreads();

    int b  = blockIdx.z;
    int c  = blockIdx.y * 8 + w;
    int p0 = blockIdx.x * 2048;

    const float4* e4  = (const float4*)enc + (((b * Cc + c) * HW + p0) >> 2);
    const uchar4* cn4 = (const uchar4*)g_conn + ((b * HW + p0) >> 2);

    float* col = acc + (w * Kk) * 32 + lane;

#pragma unroll
    for (int it = 0; it < 16; it++) {
        int idx = it * 32 + lane;
        float4 v  = e4[idx];
        uchar4 cn = cn4[idx];
        float* a;
        a = col + (int)cn.x * 32; *a = fmaxf(*a, v.x);
        a = col + (int)cn.y * 32; *a = fmaxf(*a, v.y);
        a = col + (int)cn.z * 32; *a = fmaxf(*a, v.z);
        a = col + (int)cn.w * 32; *a = fmaxf(*a, v.w);
    }

    // per-warp reduction over lanes, then one global atomicMax per (k,c)
#pragma unroll
    for (int k = 0; k < Kk; k++) {
        float m = col[k * 32];
#pragma unroll
        for (int off = 16; off; off >>= 1)
            m = fmaxf(m, __shfl_xor_sync(0xffffffffu, m, off));
        if (lane == 0)
            atomicMax((int*)&g_vec[(b * Kk + k) * Cc + c], __float_as_int(m));
    }
}

// ---------------------------------------------------------------------------
// Kernel 3 (fused head): for each bk (160 blocks, 128 threads):
//   hid[o] = b1[o] + dot(vec[bk,:], w1[o,:])        (thread o, o=0..127)
//   out[p] = sigmoid(b2[p] + dot(hid, w2[p,:]))     (warp p, p=0..3)
// vec and hid staged in shared. w1 (128KB) is L2-resident across blocks.
// ---------------------------------------------------------------------------
__global__ void k_head(const float* __restrict__ w1,
                       const float* __restrict__ b1,
                       const float* __restrict__ w2,
                       const float* __restrict__ b2,
                       float* __restrict__ out)
{
    __shared__ float s_vec[Cc];
    __shared__ float s_hid[HID];

    int bk   = blockIdx.x;          // 0..159
    int t    = threadIdx.x;         // 0..127
    int lane = t & 31;
    int p    = t >> 5;              // warp id 0..3

    // stage vec[bk]
    ((float2*)s_vec)[t] = ((const float2*)g_vec)[bk * (Cc / 2) + t];
    __syncthreads();

    // hidden: thread t computes output t
    const float4* wr = (const float4*)w1 + t * (Cc / 4);
    float s = 0.0f;
#pragma unroll
    for (int i = 0; i < Cc / 4; i++) {
        float4 a = wr[i];
        float4 x = ((const float4*)s_vec)[i];
        s += a.x * x.x + a.y * x.y + a.z * x.z + a.w * x.w;
    }
    s_hid[t] = s + b1[t];
    __syncthreads();

    // bbox: warp p computes output p via 128-length dot
    float4 h = ((const float4*)s_hid)[lane];
    float4 wv = ((const float4*)w2)[p * 32 + lane];
    float d = h.x * wv.x + h.y * wv.y + h.z * wv.z + h.w * wv.w;
#pragma unroll
    for (int off = 16; off; off >>= 1)
        d += __shfl_xor_sync(0xffffffffu, d, off);

    int b = bk / Kk;
    int k = bk % Kk;
    if (lane == 0 && k > 0) {
        float z = d + b2[p];
        out[b * ((Kk - 1) * NOUT) + (k - 1) * NOUT + p] = 1.0f / (1.0f + expf(-z));
    }
}

// ---------------------------------------------------------------------------
// Launcher. Inputs (metadata order): encoded, encoded_classes, w1, b1, w2, b2.
// Output: [out_bboxes (8*19*4=608 floats)] ++ [encoded_classes (2621440 floats)]
// ---------------------------------------------------------------------------
extern "C" void kernel_launch(void* const* d_in, const int* in_sizes, int n_in,
                              void* d_out, int out_size)
{
    const float* enc = (const float*)d_in[0];
    const float* cls = (const float*)d_in[1];
    const float* w1  = (const float*)d_in[2];
    const float* b1  = (const float*)d_in[3];
    const float* w2  = (const float*)d_in[4];
    const float* b2  = (const float*)d_in[5];

    float* out_bbox = (float*)d_out;                        // 608 floats
    float* out_cls  = (float*)d_out + Bb * (Kk - 1) * NOUT; // classes after bboxes

    // 1) argmax + classes copy + vec zeroing
    k_argmax<<<256, 256>>>(cls, out_cls);

    // 2) segment max
    dim3 g2(8, Cc / 8, Bb);
    k_segmax<<<g2, 256>>>(enc);

    // 3) fused MLP head
    k_head<<<Bb * Kk, 128>>>(w1, b1, w2, b2, out_bbox);
}

// round 8
// speedup vs baseline: 1.3714x; 1.3714x over previous
#include <cuda_runtime.h>
#include <math.h>

// Problem constants
#define Bb 8
#define Cc 256
#define Hh 128
#define Ww 128
#define Kk 20
#define HW (Hh * Ww)          // 16384
#define HID 128               // C/2
#define NOUT 4

// Scratch (device globals — no allocation allowed)
__device__ unsigned char g_conn[Bb * HW];            // argmax class per pixel
__device__ float         g_vec [Bb * Kk * Cc];       // max(segment_max, 0)

// ---------------------------------------------------------------------------
// Kernel 1: per-pixel argmax over K classes, fused with the encoded_classes
// pass-through copy into d_out, plus zeroing of g_vec.
// 65536 threads, each handles 2 consecutive pixels via float2 (256B/warp,
// fully coalesced) -> 2048 warps chip-wide, enough MLP to saturate HBM.
// ---------------------------------------------------------------------------
__global__ void k_argmax(const float* __restrict__ cls,
                         float* __restrict__ out_cls)
{
    int tid = blockIdx.x * blockDim.x + threadIdx.x;   // 0 .. 65535

    // zero the vec accumulator (40960 floats)
    if (tid < Bb * Kk * Cc)
        g_vec[tid] = 0.0f;

    int b  = tid >> 13;        // / (HW/2)
    int p2 = tid & 8191;       // % (HW/2)

    const float2* c2 = (const float2*)cls;
    float2*       o2 = (float2*)out_cls;

    float m0, m1;
    int   i0 = 0, i1 = 0;

#pragma unroll
    for (int k = 0; k < Kk; k++) {
        int idx = ((b * Kk + k) << 13) + p2;
        float2 v = c2[idx];
        o2[idx] = v;                       // pass-through copy
        if (k == 0) {
            m0 = v.x; m1 = v.y;
        } else {
            if (v.x > m0) { m0 = v.x; i0 = k; }
            if (v.y > m1) { m1 = v.y; i1 = k; }
        }
    }
    ((uchar2*)g_conn)[tid] = make_uchar2((unsigned char)i0, (unsigned char)i1);
}

// ---------------------------------------------------------------------------
// Kernel 2: segment max. grid = (8 pixel-chunks, C/8, B), block = 256 (8 warps).
// Warp w owns channel blockIdx.y*8+w. Shared acc laid out [warp][k][lane] so
// each lane only touches its own bank column -> conflict-free, atomic-free RMW.
// Accumulator starts at 0, which implements max(segmax, 0) exactly, and makes
// all values >= 0 so int atomicMax == float max.
// ---------------------------------------------------------------------------
__global__ void k_segmax(const float* __restrict__ enc)
{
    __shared__ float acc[8 * Kk * 32];     // 20 KB

    int tid  = threadIdx.x;
    int w    = tid >> 5;
    int lane = tid & 31;

    for (int i = tid; i < 8 * Kk * 32; i += 256)
        acc[i] = 0.0f;
    __syncthreads();

    int b  = blockIdx.z;
    int c  = blockIdx.y * 8 + w;
    int p0 = blockIdx.x * 2048;

    const float4* e4  = (const float4*)enc + (((b * Cc + c) * HW + p0) >> 2);
    const uchar4* cn4 = (const uchar4*)g_conn + ((b * HW + p0) >> 2);

    float* col = acc + (w * Kk) * 32 + lane;

#pragma unroll
    for (int it = 0; it < 16; it++) {
        int idx = it * 32 + lane;
        float4 v  = e4[idx];
        uchar4 cn = cn4[idx];
        float* a;
        a = col + (int)cn.x * 32; *a = fmaxf(*a, v.x);
        a = col + (int)cn.y * 32; *a = fmaxf(*a, v.y);
        a = col + (int)cn.z * 32; *a = fmaxf(*a, v.z);
        a = col + (int)cn.w * 32; *a = fmaxf(*a, v.w);
    }

    // per-warp reduction over lanes, then one global atomicMax per (k,c)
#pragma unroll
    for (int k = 0; k < Kk; k++) {
        float m = col[k * 32];
#pragma unroll
        for (int off = 16; off; off >>= 1)
            m = fmaxf(m, __shfl_xor_sync(0xffffffffu, m, off));
        if (lane == 0)
            atomicMax((int*)&g_vec[(b * Kk + k) * Cc + c], __float_as_int(m));
    }
}

// ---------------------------------------------------------------------------
// Kernel 3 (fused head): for each bk (160 blocks, 128 threads):
//   hid[o] = b1[o] + dot(vec[bk,:], w1[o,:])        (thread o, o=0..127)
//   out[p] = sigmoid(b2[p] + dot(hid, w2[p,:]))     (warp p, p=0..3)
// vec and hid staged in shared. w1 (128KB) is L2-resident across blocks.
// ---------------------------------------------------------------------------
__global__ void k_head(const float* __restrict__ w1,
                       const float* __restrict__ b1,
                       const float* __restrict__ w2,
                       const float* __restrict__ b2,
                       float* __restrict__ out)
{
    __shared__ float s_vec[Cc];
    __shared__ float s_hid[HID];

    int bk   = blockIdx.x;          // 0..159
    int t    = threadIdx.x;         // 0..127
    int lane = t & 31;
    int p    = t >> 5;              // warp id 0..3

    // stage vec[bk]
    ((float2*)s_vec)[t] = ((const float2*)g_vec)[bk * (Cc / 2) + t];
    __syncthreads();

    // hidden: thread t computes output t
    const float4* wr = (const float4*)w1 + t * (Cc / 4);
    float s = 0.0f;
#pragma unroll
    for (int i = 0; i < Cc / 4; i++) {
        float4 a = wr[i];
        float4 x = ((const float4*)s_vec)[i];
        s += a.x * x.x + a.y * x.y + a.z * x.z + a.w * x.w;
    }
    s_hid[t] = s + b1[t];
    __syncthreads();

    // bbox: warp p computes output p via 128-length dot
    float4 h = ((const float4*)s_hid)[lane];
    float4 wv = ((const float4*)w2)[p * 32 + lane];
    float d = h.x * wv.x + h.y * wv.y + h.z * wv.z + h.w * wv.w;
#pragma unroll
    for (int off = 16; off; off >>= 1)
        d += __shfl_xor_sync(0xffffffffu, d, off);

    int b = bk / Kk;
    int k = bk % Kk;
    if (lane == 0 && k > 0) {
        float z = d + b2[p];
        out[b * ((Kk - 1) * NOUT) + (k - 1) * NOUT + p] = 1.0f / (1.0f + expf(-z));
    }
}

// ---------------------------------------------------------------------------
// Launcher. Inputs (metadata order): encoded, encoded_classes, w1, b1, w2, b2.
// Output: [out_bboxes (8*19*4=608 floats)] ++ [encoded_classes (2621440 floats)]
// ---------------------------------------------------------------------------
extern "C" void kernel_launch(void* const* d_in, const int* in_sizes, int n_in,
                              void* d_out, int out_size)
{
    const float* enc = (const float*)d_in[0];
    const float* cls = (const float*)d_in[1];
    const float* w1  = (const float*)d_in[2];
    const float* b1  = (const float*)d_in[3];
    const float* w2  = (const float*)d_in[4];
    const float* b2  = (const float*)d_in[5];

    float* out_bbox = (float*)d_out;                        // 608 floats
    float* out_cls  = (float*)d_out + Bb * (Kk - 1) * NOUT; // classes after bboxes

    // 1) argmax + classes copy + vec zeroing
    k_argmax<<<256, 256>>>(cls, out_cls);

    // 2) segment max
    dim3 g2(8, Cc / 8, Bb);
    k_segmax<<<g2, 256>>>(enc);

    // 3) fused MLP head
    k_head<<<Bb * Kk, 128>>>(w1, b1, w2, b2, out_bbox);
}